// round 12
// baseline (speedup 1.0000x reference)
#include <cuda_runtime.h>
#include <cstddef>

// Problem constants (bigram trie, fixed shapes from reference)
#define V_  32768
#define C_  32
#define B_  32
#define K_  (V_ * C_)        // 1048576 bigram nodes
#define X_  (K_ + 1)         // pointers length
#define G_  V_               // unigram count
#define U_  (V_ + 1)         // first bigram node index

// Fused fill + inline override, single-barrier version:
//  - grid = 1024 blocks (32 rows x 32 v-chunks), 256 threads, 1 float4/thread
//  - warp 0 walks the uniform chain (idx -> h -> backoff/pointers -> ids/logs)
//    and publishes backoff + an in-window override list {tok, lp} via smem
//  - ONE __syncthreads; then every thread patches its 4 registers from the
//    (avg length 1) list and issues a single float4 store. No second barrier,
//    no separate override store pass.
__global__ void __launch_bounds__(256) llm_fused_kernel(
    const int* __restrict__ hist,
    const int* __restrict__ idx,
    const int* __restrict__ pointers,
    const int* __restrict__ ids,
    const float* __restrict__ logs,
    float* __restrict__ out)
{
    __shared__ float s_back;
    __shared__ int   s_cnt;
    __shared__ int   s_ptok[C_];
    __shared__ float s_plp[C_];

    const int blk   = blockIdx.x;          // 0..1023
    const int b     = blk >> 5;            // row (32 chunks per row)
    const int chunk = blk & 31;
    const int tid   = threadIdx.x;
    const int v0    = chunk * 1024 + tid * 4;

    // Every thread: its own fill data, issued immediately.
    const float4 lv = *reinterpret_cast<const float4*>(logs + v0);

    // Warp 0: uniform chain + override list build. Other warps go straight
    // to the barrier (their only load is already in flight).
    if (tid < 32) {
        if (tid == 0) s_cnt = 0;
        __syncwarp();
        const int h   = __ldg(hist + (__ldg(idx) - 1) * B_ + b);
        const int off = __ldg(pointers + h);
        const int nc  = __ldg(pointers + h + 1) - off + 1;
        if (tid == 0)
            s_back = __ldg(logs + (size_t)X_ + G_ + h);
        if (tid < nc) {
            const int node = h + off + tid;           // bigram node id
            const int tok  = __ldg(ids + (node - U_));// child token id
            if ((tok >> 10) == chunk) {               // in this block's window
                const float lp = __ldg(logs + node);  // bigram log-prob
                const int i = atomicAdd(&s_cnt, 1);
                s_ptok[i] = tok;
                s_plp[i]  = lp;
            }
        }
    }

    __syncthreads();   // s_back + override list ready

    const float backoff = s_back;
    float r0 = backoff + lv.x;
    float r1 = backoff + lv.y;
    float r2 = backoff + lv.z;
    float r3 = backoff + lv.w;

    // Patch from the (avg length 1) override list.
    const int n = s_cnt;
    for (int i = 0; i < n; i++) {
        const unsigned d = (unsigned)(s_ptok[i] - v0);
        if (d < 4u) {
            const float lp = s_plp[i];
            r0 = (d == 0u) ? lp : r0;
            r1 = (d == 1u) ? lp : r1;
            r2 = (d == 2u) ? lp : r2;
            r3 = (d == 3u) ? lp : r3;
        }
    }

    float4 o; o.x = r0; o.y = r1; o.z = r2; o.w = r3;
    *reinterpret_cast<float4*>(out + (size_t)b * V_ + v0) = o;
}

extern "C" void kernel_launch(void* const* d_in, const int* in_sizes, int n_in,
                              void* d_out, int out_size)
{
    const int*   hist     = (const int*)d_in[0];   // (S, B) int32
    const int*   idx      = (const int*)d_in[1];   // scalar int32
    const int*   pointers = (const int*)d_in[2];   // (X,) int32
    const int*   ids      = (const int*)d_in[3];   // (K,) int32
    const float* logs     = (const float*)d_in[4]; // (L,) float32
    float*       out      = (float*)d_out;         // (B, V) float32

    (void)in_sizes; (void)n_in; (void)out_size;

    llm_fused_kernel<<<(B_ * V_) / (256 * 4), 256>>>(hist, idx, pointers, ids, logs, out);
}